// round 1
// baseline (speedup 1.0000x reference)
#include <cuda_runtime.h>
#include <cstdint>

// MixtureCrossattention: per batch b,
//   C = [e1 | e2]  (16 x 576),  e = patch_embed(x)
//   x3[:,q] = sum_p lam3(p) * softmax_p(e2[:,q]·C[:,p]) * C[:,p]   (lam3 = 0.7 for p<288 else 0.3)
//   x4[:,q] = sum_p lam4(p) * softmax_p(e1[:,q]·C[:,p]) * C[:,p]   (lam4 = 0.3 for p<288 else 0.7)
// (the reference's batch-0 block-transpose is a no-op: the e2^T e2 block is symmetric)
//
// One CTA per (batch, half). 288 threads, one query per thread.
// Keys in smem as float2 pairs of adjacent columns; all math in packed f32x2.

#define LOG2E 1.4426950408889634f

__device__ __forceinline__ unsigned long long pack2(float lo, float hi) {
    unsigned long long r;
    asm("mov.b64 %0, {%1, %2};" : "=l"(r) : "f"(lo), "f"(hi));
    return r;
}
__device__ __forceinline__ void unpack2(unsigned long long v, float &lo, float &hi) {
    asm("mov.b64 {%0, %1}, %2;" : "=f"(lo), "=f"(hi) : "l"(v));
}
__device__ __forceinline__ unsigned long long fma2(unsigned long long a, unsigned long long b, unsigned long long c) {
    unsigned long long d;
    asm("fma.rn.f32x2 %0, %1, %2, %3;" : "=l"(d) : "l"(a), "l"(b), "l"(c));
    return d;
}
__device__ __forceinline__ unsigned long long add2(unsigned long long a, unsigned long long b) {
    unsigned long long d;
    asm("add.rn.f32x2 %0, %1, %2;" : "=l"(d) : "l"(a), "l"(b));
    return d;
}
__device__ __forceinline__ unsigned long long mul2(unsigned long long a, unsigned long long b) {
    unsigned long long d;
    asm("mul.rn.f32x2 %0, %1, %2;" : "=l"(d) : "l"(a), "l"(b));
    return d;
}
__device__ __forceinline__ float ex2a(float x) {
    float y;
    asm("ex2.approx.f32 %0, %1;" : "=f"(y) : "f"(x));
    return y;
}

__global__ __launch_bounds__(288, 2)
void mixca_kernel(const float* __restrict__ x1,
                  const float* __restrict__ x2,
                  float* __restrict__ out)
{
    // Row jp (128B): 16 float2 = (C[i][2jp], C[i][2jp+1]), i = 0..15
    __shared__ __align__(16) float sK[288 * 32];

    const int b    = blockIdx.x;
    const int half = blockIdx.y;   // 0 -> x3, 1 -> x4
    const int t    = threadIdx.x;  // query column 0..287

    // ---- Load + patch-embed both inputs into sK (pair layout) ----
    {
        const float* src0 = x1 + (size_t)b * 4608;
        const float* src1 = x2 + (size_t)b * 4608;
        #pragma unroll
        for (int e = 0; e < 2; e++) {
            const float* src = (e == 0) ? src0 : src1;
            #pragma unroll
            for (int k = 0; k < 16; k++) {
                int g = t + k * 288;           // linear idx into [32][12][12]
                float v = src[g];
                int c   = g / 144;
                int rem = g - c * 144;
                int r   = rem / 12;
                int s   = rem - r * 12;
                int h = r / 3, p1 = r - h * 3;
                int w = s / 3, p2 = s - w * 3;
                int i = h * 4 + w;                        // 0..15
                int j = (p1 * 3 + p2) * 32 + c + e * 288; // 0..575
                sK[(j >> 1) * 32 + i * 2 + (j & 1)] = v;
            }
        }
    }
    __syncthreads();

    // ---- Query vector (pre-scaled by log2 e), duplicated into both halves ----
    const int qcol = (half == 0) ? (288 + t) : t;   // x3 uses e2 queries, x4 uses e1
    unsigned long long qv[16];
    {
        const float* qptr = &sK[(qcol >> 1) * 32 + (qcol & 1)];
        #pragma unroll
        for (int i = 0; i < 16; i++) {
            float q = qptr[i * 2] * LOG2E;
            qv[i] = pack2(q, q);
        }
    }

    unsigned long long acc[16];
    #pragma unroll
    for (int i = 0; i < 16; i++) acc[i] = 0ull;   // packed (0,0)
    unsigned long long sum2 = 0ull;

    const float lamA = (half == 0) ? 0.7f : 0.3f; // keys 0..287 (e1 block)
    const float lamB = 1.0f - lamA;               // keys 288..575 (e2 block)

    #pragma unroll 1
    for (int seg = 0; seg < 2; seg++) {
        const float lamseg = seg ? lamB : lamA;
        const unsigned long long lam2 = pack2(lamseg, lamseg);
        const int jp0 = seg * 144;
        #pragma unroll 1
        for (int jp = jp0; jp < jp0 + 144; jp++) {
            const ulonglong2* row = reinterpret_cast<const ulonglong2*>(&sK[jp * 32]);
            // scores for key columns (2jp, 2jp+1), two chains for ILP
            unsigned long long sA = 0ull, sB = 0ull;
            #pragma unroll
            for (int u = 0; u < 8; u++) {
                ulonglong2 kk = row[u];
                sA = fma2(qv[2 * u],     kk.x, sA);
                sB = fma2(qv[2 * u + 1], kk.y, sB);
            }
            unsigned long long s2 = add2(sA, sB);
            float slo, shi;
            unpack2(s2, slo, shi);
            float wlo = ex2a(slo);
            float whi = ex2a(shi);
            unsigned long long w2 = pack2(wlo, whi);
            sum2 = add2(sum2, w2);
            unsigned long long wl2 = mul2(w2, lam2);
            // accumulate lam * w * key  (reload keys from smem; keeps regs low)
            #pragma unroll
            for (int u = 0; u < 8; u++) {
                ulonglong2 kk = row[u];
                acc[2 * u]     = fma2(wl2, kk.x, acc[2 * u]);
                acc[2 * u + 1] = fma2(wl2, kk.y, acc[2 * u + 1]);
            }
        }
    }

    float s_lo, s_hi;
    unpack2(sum2, s_lo, s_hi);
    const float inv = 1.0f / (s_lo + s_hi);

    __syncthreads();          // everyone done reading sK; reuse as staging
    float* sO = sK;           // [288][17] padded
    #pragma unroll
    for (int i = 0; i < 16; i++) {
        float a_lo, a_hi;
        unpack2(acc[i], a_lo, a_hi);
        sO[t * 17 + i] = (a_lo + a_hi) * inv;
    }
    __syncthreads();

    // ---- Coalesced un-patch store: out layout (x3 block, then x4 block) ----
    float* dst = out + ((size_t)half * 512 + (size_t)b) * 4608;
    #pragma unroll
    for (int k = 0; k < 16; k++) {
        int g = t + k * 288;
        int c   = g / 144;
        int rem = g - c * 144;
        int r   = rem / 12;
        int s   = rem - r * 12;
        int h = r / 3, p1 = r - h * 3;
        int w = s / 3, p2 = s - w * 3;
        int i  = h * 4 + w;
        int tt = (p1 * 3 + p2) * 32 + c;
        dst[g] = sO[tt * 17 + i];
    }
}

extern "C" void kernel_launch(void* const* d_in, const int* in_sizes, int n_in,
                              void* d_out, int out_size)
{
    const float* x1 = (const float*)d_in[0];
    const float* x2 = (const float*)d_in[1];
    float* out = (float*)d_out;
    dim3 grid(512, 2);
    mixca_kernel<<<grid, 288>>>(x1, x2, out);
}